// round 1
// baseline (speedup 1.0000x reference)
#include <cuda_runtime.h>
#include <math.h>
#include <stdint.h>

// Problem constants
#define NB 32      // batch
#define C 128      // channels
#define HW 4096    // H*W
#define K 64       // clusters
#define KE 56      // effective clusters (64 - 8 ghost)
#define TP 128     // pixels per tile
#define SPLITS 8   // pixel splits per image
#define TILES_PER_BLOCK (HW / SPLITS / TP)  // 4
#define NTHR 256

#define XS_STRIDE 129
#define LS_STRIDE 129

// Dynamic smem layout (floats)
#define XS_OFF 0
#define XS_SZ (C * XS_STRIDE)          // 16512
#define WST_OFF (XS_OFF + XS_SZ)
#define WST_SZ (C * K)                 // 8192
#define LS_OFF (WST_OFF + WST_SZ)
#define LS_SZ (K * LS_STRIDE)          // 8256
#define SMEM_FLOATS (LS_OFF + LS_SZ)
#define SMEM_BYTES (SMEM_FLOATS * 4)   // 131840 bytes

// Scratch (device globals -- no allocation allowed)
__device__ float g_vlad[NB * KE * C];  // 229376
__device__ float g_asum[NB * KE];      // 1792

__global__ void zero_scratch() {
    int idx = blockIdx.x * blockDim.x + threadIdx.x;
    if (idx < NB * KE * C) g_vlad[idx] = 0.0f;
    if (idx < NB * KE) g_asum[idx] = 0.0f;
}

__global__ __launch_bounds__(NTHR, 1)
void netvlad_main(const float* __restrict__ x,
                  const float* __restrict__ conv_w,
                  const float* __restrict__ conv_b) {
    extern __shared__ float sm[];
    float* xs  = sm + XS_OFF;   // [C][XS_STRIDE]  x tile (then xn, in place)
    float* wst = sm + WST_OFF;  // [C][K]          W transposed
    float* ls  = sm + LS_OFF;   // [K][LS_STRIDE]  logits -> assignments

    __shared__ float bs[K];
    __shared__ float rn[TP];
    __shared__ float colss[TP];
    __shared__ float asum_s[KE];

    const int n     = blockIdx.x;
    const int split = blockIdx.y;
    const int tid   = threadIdx.x;
    const int lane  = tid & 31;
    const int w     = tid >> 5;

    // Load W^T (wst[c][k] = conv_w[k][c]) and bias; init per-block asum
    for (int idx = tid; idx < K * C; idx += NTHR) {
        int k = idx >> 7, c = idx & 127;
        wst[c * K + k] = conv_w[idx];
    }
    if (tid < K) bs[tid] = conv_b[tid];
    if (tid < KE) asum_s[tid] = 0.0f;

    // Persistent VLAD accumulators: warp w owns k = w*7..w*7+6, lane owns c = lane + 32j
    float vacc[7][4];
#pragma unroll
    for (int i = 0; i < 7; ++i)
#pragma unroll
        for (int j = 0; j < 4; ++j) vacc[i][j] = 0.0f;

    const float* xbase = x + (size_t)n * C * HW + split * (HW / SPLITS);

    for (int tile = 0; tile < TILES_PER_BLOCK; ++tile) {
        const float* xt = xbase + tile * TP;
        __syncthreads();  // previous tile's GEMM2 done reading xs/ls

        // ---- Load x tile (coalesced, vectorized) ----
        for (int idx = tid; idx < C * (TP / 4); idx += NTHR) {
            int c = idx >> 5, p4 = idx & 31;
            float4 v = __ldg((const float4*)(xt + (size_t)c * HW) + p4);
            float* dst = xs + c * XS_STRIDE + p4 * 4;
            dst[0] = v.x; dst[1] = v.y; dst[2] = v.z; dst[3] = v.w;
        }
        __syncthreads();

        // ---- Per-pixel rnorm over C, then scale xs in place -> xn ----
        {
            int p = tid & 127, h = tid >> 7;
            float ss = 0.0f;
            for (int c = h * 64; c < h * 64 + 64; ++c) {
                float v = xs[c * XS_STRIDE + p];
                ss += v * v;
            }
            if (h == 0) colss[p] = ss;
            __syncthreads();
            if (h == 1) colss[p] += ss;
            __syncthreads();
            if (tid < TP) rn[tid] = 1.0f / fmaxf(sqrtf(colss[tid]), 1e-12f);
            __syncthreads();
            for (int idx = tid; idx < C * TP; idx += NTHR) {
                int c = idx >> 7, pp = idx & 127;
                xs[c * XS_STRIDE + pp] *= rn[pp];
            }
            __syncthreads();
        }

        // ---- GEMM1: logits[64][128] = W @ xn ----
        // warp w -> k rows w*8..w*8+7 ; lane -> p = lane + 32j
        {
            float acc1[8][4];
#pragma unroll
            for (int i = 0; i < 8; ++i)
#pragma unroll
                for (int j = 0; j < 4; ++j) acc1[i][j] = 0.0f;

            const int kbase = w * 8;
            for (int c = 0; c < C; ++c) {
                float wk[8], xp[4];
#pragma unroll
                for (int i = 0; i < 8; ++i) wk[i] = wst[c * K + kbase + i];  // broadcast
#pragma unroll
                for (int j = 0; j < 4; ++j) xp[j] = xs[c * XS_STRIDE + lane + 32 * j];
#pragma unroll
                for (int i = 0; i < 8; ++i)
#pragma unroll
                    for (int j = 0; j < 4; ++j) acc1[i][j] += wk[i] * xp[j];
            }
            // write logits + bias
#pragma unroll
            for (int i = 0; i < 8; ++i) {
                int k = kbase + i;
                float b = bs[k];
#pragma unroll
                for (int j = 0; j < 4; ++j)
                    ls[k * LS_STRIDE + lane + 32 * j] = acc1[i][j] + b;
            }
        }
        __syncthreads();

        // ---- Softmax over k per pixel column (threads 0..127, 3 smem passes) ----
        if (tid < TP) {
            const int p = tid;
            float m = -1e30f;
#pragma unroll
            for (int k = 0; k < K; ++k) m = fmaxf(m, ls[k * LS_STRIDE + p]);
            float s = 0.0f;
#pragma unroll
            for (int k = 0; k < K; ++k) {
                float e = __expf(ls[k * LS_STRIDE + p] - m);
                ls[k * LS_STRIDE + p] = e;  // own column only, no race
                s += e;
            }
            float inv = 1.0f / s;
#pragma unroll
            for (int k = 0; k < KE; ++k) ls[k * LS_STRIDE + p] *= inv;
        }
        __syncthreads();

        // ---- asum: warp w reduces rows w*7..w*7+6 ----
#pragma unroll
        for (int i = 0; i < 7; ++i) {
            int k = w * 7 + i;
            float sv = 0.0f;
#pragma unroll
            for (int j = 0; j < 4; ++j) sv += ls[k * LS_STRIDE + lane + 32 * j];
#pragma unroll
            for (int off = 16; off; off >>= 1) sv += __shfl_down_sync(0xffffffffu, sv, off);
            if (lane == 0) asum_s[k] += sv;
        }
        // (warp w reads only its own rows next; cross-warp ls/xs already synced)

        // ---- GEMM2: vlad[56][128] += A[56][TP] @ xn^T[TP][128] ----
        // warp w -> k rows w*7..w*7+6 ; lane -> c = lane + 32j
        for (int p = 0; p < TP; ++p) {
            float ak[7], xv[4];
#pragma unroll
            for (int i = 0; i < 7; ++i) ak[i] = ls[(w * 7 + i) * LS_STRIDE + p];  // broadcast
#pragma unroll
            for (int j = 0; j < 4; ++j) xv[j] = xs[(lane + 32 * j) * XS_STRIDE + p];
#pragma unroll
            for (int i = 0; i < 7; ++i)
#pragma unroll
                for (int j = 0; j < 4; ++j) vacc[i][j] += ak[i] * xv[j];
        }
    }

    __syncthreads();
    // ---- Flush partials ----
    float* gv = g_vlad + (size_t)n * KE * C;
#pragma unroll
    for (int i = 0; i < 7; ++i) {
        int k = w * 7 + i;
#pragma unroll
        for (int j = 0; j < 4; ++j) {
            int c = lane + 32 * j;
            atomicAdd(&gv[k * C + c], vacc[i][j]);
        }
    }
    if (tid < KE) atomicAdd(&g_asum[n * KE + tid], asum_s[tid]);
}

__global__ __launch_bounds__(NTHR)
void netvlad_finalize(const float* __restrict__ centroids, float* __restrict__ out) {
    __shared__ float ys[KE * C];   // 28 KB
    __shared__ float colinv[C];
    __shared__ float asl[KE];
    __shared__ float red[8];
    __shared__ float s_inv2;

    const int n = blockIdx.x;
    const int tid = threadIdx.x;

    if (tid < KE) asl[tid] = g_asum[n * KE + tid];
    __syncthreads();

    const int c = tid & 127, h = tid >> 7;
    const float* gv = g_vlad + (size_t)n * KE * C;
    float ss = 0.0f;
#pragma unroll
    for (int i = 0; i < 28; ++i) {
        int k = h * 28 + i;
        float y = gv[k * C + c] - asl[k] * centroids[k * C + c];
        ys[k * C + c] = y;
        ss += y * y;
    }
    if (h == 0) colinv[c] = ss;
    __syncthreads();
    if (h == 1) colinv[c] += ss;
    __syncthreads();

    float gs = 0.0f;
    if (tid < C) {
        float cs = colinv[tid];
        float i1 = 1.0f / fmaxf(sqrtf(cs), 1e-12f);
        gs = cs * i1 * i1;         // sum of z^2 contributed by this column
        colinv[tid] = i1;
    }
    __syncthreads();
#pragma unroll
    for (int off = 16; off; off >>= 1) gs += __shfl_down_sync(0xffffffffu, gs, off);
    if ((tid & 31) == 0) red[tid >> 5] = gs;
    __syncthreads();
    if (tid == 0) {
        float t = 0.0f;
#pragma unroll
        for (int i = 0; i < 8; ++i) t += red[i];
        s_inv2 = 1.0f / fmaxf(sqrtf(t), 1e-12f);
    }
    __syncthreads();
    const float inv2 = s_inv2;
    float* op = out + (size_t)n * KE * C;
    for (int idx = tid; idx < KE * C; idx += NTHR)
        op[idx] = ys[idx] * colinv[idx & 127] * inv2;
}

extern "C" void kernel_launch(void* const* d_in, const int* in_sizes, int n_in,
                              void* d_out, int out_size) {
    const float* x      = (const float*)d_in[0];
    const float* conv_w = (const float*)d_in[1];
    const float* conv_b = (const float*)d_in[2];
    const float* cen    = (const float*)d_in[3];
    float* out = (float*)d_out;

    cudaFuncSetAttribute(netvlad_main, cudaFuncAttributeMaxDynamicSharedMemorySize, SMEM_BYTES);

    int zn = NB * KE * C;  // 229376 covers g_asum too
    zero_scratch<<<(zn + 255) / 256, 256>>>();
    netvlad_main<<<dim3(NB, SPLITS), NTHR, SMEM_BYTES>>>(x, conv_w, conv_b);
    netvlad_finalize<<<NB, NTHR>>>(cen, out);
}

// round 2
// speedup vs baseline: 1.1129x; 1.1129x over previous
#include <cuda_runtime.h>
#include <math.h>
#include <stdint.h>

typedef unsigned long long ull;

// Problem constants
#define NB 32      // batch
#define C 128      // channels
#define HW 4096    // H*W
#define K 64       // clusters
#define KE 56      // effective clusters
#define TP 128     // pixels per tile
#define NTILES (HW / TP)   // 32 tiles per image
#define NTHR 256

#define STRIDE 130  // row stride (floats): 130 mod 32 == 2 -> conflict-free LDS.64 column access

// Dynamic smem layout (floats)
#define XS_OFF  0
#define XS_SZ   (C * STRIDE)            // 16640  raw x  [c][p]
#define XT_OFF  (XS_OFF + XS_SZ)
#define XT_SZ   (TP * STRIDE)           // 16640  raw x^T [p][c]
#define WS_OFF  (XT_OFF + XT_SZ)
#define WS_SZ   (K * C)                 // 8192   W [k][c] (natural layout)
#define LS_OFF  (WS_OFF + WS_SZ)
#define LS_SZ   (K * STRIDE)            // 8320   logits -> assignments
#define SMEM_FLOATS (LS_OFF + LS_SZ)    // 49792
#define SMEM_BYTES  (SMEM_FLOATS * 4)   // 199168

// Scratch (device globals -- no allocation allowed)
__device__ float g_vlad[NB * KE * C];
__device__ float g_asum[NB * KE];

__global__ void zero_scratch() {
    int idx = blockIdx.x * blockDim.x + threadIdx.x;
    if (idx < NB * KE * C) g_vlad[idx] = 0.0f;
    if (idx < NB * KE) g_asum[idx] = 0.0f;
}

// packed dual-fp32 FMA (sm_100a): d = a*b + c elementwise on a 64-bit f32x2
__device__ __forceinline__ ull ffma2(ull a, ull b, ull c) {
    ull d;
    asm("fma.rn.f32x2 %0, %1, %2, %3;" : "=l"(d) : "l"(a), "l"(b), "l"(c));
    return d;
}
__device__ __forceinline__ float f2sum(ull v) {
    float lo = __uint_as_float((unsigned)(v & 0xffffffffull));
    float hi = __uint_as_float((unsigned)(v >> 32));
    return lo + hi;
}

__global__ __launch_bounds__(NTHR, 1)
void netvlad_main(const float* __restrict__ x,
                  const float* __restrict__ conv_w,
                  const float* __restrict__ conv_b) {
    extern __shared__ float sm[];
    float* xs  = sm + XS_OFF;   // [C][STRIDE]  raw x tile
    float* xsT = sm + XT_OFF;   // [TP][STRIDE] raw x transposed
    float* wsm = sm + WS_OFF;   // [K][C]
    float* ls  = sm + LS_OFF;   // [K][STRIDE]

    __shared__ float bs[K];
    __shared__ float rn[TP];        // 1/max(||x_p||, eps)
    __shared__ float sinv[TP];      // 1/softmax-sum per pixel
    __shared__ float mred[2 * TP];  // softmax max halves
    __shared__ float sred[2 * TP];  // softmax sum halves

    const int n    = blockIdx.x;
    const int tile = blockIdx.y;
    const int tid  = threadIdx.x;
    const int lane = tid & 31;
    const int w    = tid >> 5;

    // ---- Load W (natural [k][c] layout) and bias ----
    {
        const float4* src = (const float4*)conv_w;
        float4* dst = (float4*)wsm;
        for (int i = tid; i < (K * C) / 4; i += NTHR) dst[i] = __ldg(src + i);
        if (tid < K) bs[tid] = conv_b[tid];
    }

    // ---- Load raw x tile: GMEM [c][p] -> xs[c][p] ----
    const float* xt = x + (size_t)n * C * HW + tile * TP;
    for (int idx = tid; idx < C * (TP / 4); idx += NTHR) {
        int c = idx >> 5, p4 = idx & 31;
        float4 v = __ldg((const float4*)(xt + (size_t)c * HW) + p4);
        float* dst = xs + c * STRIDE + p4 * 4;
        *(ull*)(dst)     = *(ull*)&v.x;
        *(ull*)(dst + 2) = *(ull*)&v.z;
    }
    __syncthreads();

    // ---- Transpose xs -> xsT, fused with sum-of-squares per pixel ----
    {
        const int p = tid & 127, h = tid >> 7;
        float ss = 0.0f;
        const int c0 = h * 64;
#pragma unroll 8
        for (int i = 0; i < 64; ++i) {
            int c = c0 + i;
            float v = xs[c * STRIDE + p];
            ss += v * v;
            xsT[p * STRIDE + c] = v;
        }
        mred[h * TP + p] = ss;  // reuse mred as ssq scratch
        __syncthreads();
        if (tid < TP) {
            float tot = mred[tid] + mred[TP + tid];
            rn[tid] = 1.0f / fmaxf(sqrtf(tot), 1e-12f);
        }
    }
    __syncthreads();

    // ---- GEMM1: logits[64][128] = (W @ x) * rn + b  (f32x2 paired over c) ----
    {
        const int kbase = w * 8;
        ull acc[8][4];
#pragma unroll
        for (int i = 0; i < 8; ++i)
#pragma unroll
            for (int j = 0; j < 4; ++j) acc[i][j] = 0ull;

        const float* wp = wsm + kbase * C;
        const float* xp0 = xsT + lane * STRIDE;
#pragma unroll 2
        for (int c2 = 0; c2 < C / 2; ++c2) {
            ull wk[8], xp[4];
#pragma unroll
            for (int i = 0; i < 8; ++i) wk[i] = *(const ull*)(wp + i * C + 2 * c2);       // broadcast
#pragma unroll
            for (int j = 0; j < 4; ++j) xp[j] = *(const ull*)(xp0 + j * 32 * STRIDE + 2 * c2);
#pragma unroll
            for (int i = 0; i < 8; ++i)
#pragma unroll
                for (int j = 0; j < 4; ++j) acc[i][j] = ffma2(wk[i], xp[j], acc[i][j]);
        }
        // epilogue: logits = dot * rn[p] + b
        float rnj[4];
#pragma unroll
        for (int j = 0; j < 4; ++j) rnj[j] = rn[lane + 32 * j];
#pragma unroll
        for (int i = 0; i < 8; ++i) {
            float b = bs[kbase + i];
#pragma unroll
            for (int j = 0; j < 4; ++j)
                ls[(kbase + i) * STRIDE + lane + 32 * j] = f2sum(acc[i][j]) * rnj[j] + b;
        }
    }
    __syncthreads();

    // ---- Softmax over k per pixel (256 threads: two k-halves) ----
    {
        const int p = tid & 127, h = tid >> 7;
        const int k0 = h * 32;
        float m = -1e30f;
#pragma unroll 8
        for (int i = 0; i < 32; ++i) m = fmaxf(m, ls[(k0 + i) * STRIDE + p]);
        mred[h * TP + p] = m;
        __syncthreads();
        float M = fmaxf(mred[p], mred[TP + p]);
        float s = 0.0f;
#pragma unroll 8
        for (int i = 0; i < 32; ++i) {
            float e = __expf(ls[(k0 + i) * STRIDE + p] - M);
            ls[(k0 + i) * STRIDE + p] = e;
            s += e;
        }
        sred[h * TP + p] = s;
        __syncthreads();
        if (tid < TP) sinv[tid] = 1.0f / (sred[tid] + sred[TP + tid]);
    }
    __syncthreads();

    // ---- asum (uses a = e*sinv) + fold rn into assignments (a' = a*rn) ----
    {
        const int kb = w * 7;
        float si[4], sir[4];
#pragma unroll
        for (int j = 0; j < 4; ++j) {
            int p = lane + 32 * j;
            si[j] = sinv[p];
            sir[j] = si[j] * rn[p];
        }
#pragma unroll
        for (int i = 0; i < 7; ++i) {
            float sv = 0.0f;
#pragma unroll
            for (int j = 0; j < 4; ++j) {
                float* ap = ls + (kb + i) * STRIDE + lane + 32 * j;
                float e = *ap;
                sv += e * si[j];
                *ap = e * sir[j];
            }
#pragma unroll
            for (int off = 16; off; off >>= 1) sv += __shfl_down_sync(0xffffffffu, sv, off);
            if (lane == 0) atomicAdd(&g_asum[n * KE + kb + i], sv);
        }
    }
    __syncthreads();

    // ---- GEMM2: vlad[56][128] += a' @ x^T  (f32x2 paired over p) ----
    {
        const int kb = w * 7;
        ull vacc[7][4];
#pragma unroll
        for (int i = 0; i < 7; ++i)
#pragma unroll
            for (int j = 0; j < 4; ++j) vacc[i][j] = 0ull;

        const float* ap0 = ls + kb * STRIDE;
        const float* xv0 = xs + lane * STRIDE;
#pragma unroll 2
        for (int p2 = 0; p2 < TP / 2; ++p2) {
            ull ak[7], xv[4];
#pragma unroll
            for (int i = 0; i < 7; ++i) ak[i] = *(const ull*)(ap0 + i * STRIDE + 2 * p2);  // broadcast
#pragma unroll
            for (int j = 0; j < 4; ++j) xv[j] = *(const ull*)(xv0 + j * 32 * STRIDE + 2 * p2);
#pragma unroll
            for (int i = 0; i < 7; ++i)
#pragma unroll
                for (int j = 0; j < 4; ++j) vacc[i][j] = ffma2(ak[i], xv[j], vacc[i][j]);
        }
        // flush partials
        float* gv = g_vlad + (size_t)n * KE * C;
#pragma unroll
        for (int i = 0; i < 7; ++i)
#pragma unroll
            for (int j = 0; j < 4; ++j)
                atomicAdd(&gv[(kb + i) * C + lane + 32 * j], f2sum(vacc[i][j]));
    }
}

__global__ __launch_bounds__(NTHR)
void netvlad_finalize(const float* __restrict__ centroids, float* __restrict__ out) {
    __shared__ float ys[KE * C];
    __shared__ float colinv[C];
    __shared__ float asl[KE];
    __shared__ float red[8];
    __shared__ float s_inv2;

    const int n = blockIdx.x;
    const int tid = threadIdx.x;

    if (tid < KE) asl[tid] = g_asum[n * KE + tid];
    __syncthreads();

    const int c = tid & 127, h = tid >> 7;
    const float* gv = g_vlad + (size_t)n * KE * C;
    float ss = 0.0f;
#pragma unroll
    for (int i = 0; i < 28; ++i) {
        int k = h * 28 + i;
        float y = gv[k * C + c] - asl[k] * centroids[k * C + c];
        ys[k * C + c] = y;
        ss += y * y;
    }
    if (h == 0) colinv[c] = ss;
    __syncthreads();
    if (h == 1) colinv[c] += ss;
    __syncthreads();

    float gs = 0.0f;
    if (tid < C) {
        float cs = colinv[tid];
        float i1 = 1.0f / fmaxf(sqrtf(cs), 1e-12f);
        gs = cs * i1 * i1;
        colinv[tid] = i1;
    }
    __syncthreads();
#pragma unroll
    for (int off = 16; off; off >>= 1) gs += __shfl_down_sync(0xffffffffu, gs, off);
    if ((tid & 31) == 0) red[tid >> 5] = gs;
    __syncthreads();
    if (tid == 0) {
        float t = 0.0f;
#pragma unroll
        for (int i = 0; i < 8; ++i) t += red[i];
        s_inv2 = 1.0f / fmaxf(sqrtf(t), 1e-12f);
    }
    __syncthreads();
    const float inv2 = s_inv2;
    float* op = out + (size_t)n * KE * C;
    for (int idx = tid; idx < KE * C; idx += NTHR)
        op[idx] = ys[idx] * colinv[idx & 127] * inv2;
}

extern "C" void kernel_launch(void* const* d_in, const int* in_sizes, int n_in,
                              void* d_out, int out_size) {
    const float* x      = (const float*)d_in[0];
    const float* conv_w = (const float*)d_in[1];
    const float* conv_b = (const float*)d_in[2];
    const float* cen    = (const float*)d_in[3];
    float* out = (float*)d_out;

    cudaFuncSetAttribute(netvlad_main, cudaFuncAttributeMaxDynamicSharedMemorySize, SMEM_BYTES);

    int zn = NB * KE * C;
    zero_scratch<<<(zn + 255) / 256, 256>>>();
    netvlad_main<<<dim3(NB, NTILES), NTHR, SMEM_BYTES>>>(x, conv_w, conv_b);
    netvlad_finalize<<<NB, NTHR>>>(cen, out);
}